// round 2
// baseline (speedup 1.0000x reference)
#include <cuda_runtime.h>
#include <stdint.h>

// SRP map on GB300 — round 2.
//
// maps[f,g] = sum_{p<144} x[f, p, tau0[p,g]]  (tau wrapped lags all in
// {0..7} U {504..511} -> 16 "slots"), then per-frame zero-mean + /max.
//
// R2 changes vs R1 (which was latency-bound at 20.7% occupancy):
//  * Grid-point split: CTA = (frame, quarter of the 2048 grid points).
//    grid 256 -> 1024 CTAs (~4x warp parallelism). Normalization moves to a
//    tiny second kernel (per-frame, in-place on d_out). No atomics.
//  * Within a CTA, 4 thread-subsets each cover 36 of the 144 pairs and are
//    reduced through smem (same buffer reused, conflict-free stride-9).
//  * tau prepacked as BYTES holding slot*4 (direct LDS byte offset),
//    transposed so each thread reads 72 contiguous uint32 (18x LDG.128).
//    Inner loop per point-pair: PRMT + IADD + LDS + FADD (4 instr).
//  * xsm[p*16 + slot]: warp-LDS lanes share p, differ in slot ->
//    distinct banks -> conflict-free.

#define NPAIR   144
#define KLEN    512
#define GPTS    2048
#define THREADS 256
#define NSPLIT  4            // grid-point quarters per frame
#define PSUB    (NPAIR / 4)  // 36 pairs per thread-subset

// Packed tau byte-offsets: word index i = (g8*144 + p)*2 + h,
// where g8 = 8-point group (0..255), h selects points 4h..4h+3 of the group.
// Each byte = (tau & 15) * 4  (LDS byte offset of the slot within a pair row).
__device__ uint32_t g_tauB[256 * NPAIR * 2];

__global__ void __launch_bounds__(256) pre_pack_kernel(const int* __restrict__ tau0) {
    int i = blockIdx.x * blockDim.x + threadIdx.x;
    if (i >= 256 * NPAIR * 2) return;
    int g8  = i / (NPAIR * 2);
    int rem = i - g8 * (NPAIR * 2);
    int p   = rem >> 1;
    int h   = rem & 1;
    int pt  = g8 * 8 + h * 4;
    const int* tp = tau0 + p * GPTS + pt;
    uint32_t v = 0;
#pragma unroll
    for (int j = 0; j < 4; j++) {
        uint32_t b = ((uint32_t)tp[j] & 15u) << 2;   // slot*4, <= 60
        v |= b << (8 * j);
    }
    g_tauB[i] = v;
}

// ---------------- main gather kernel ----------------
// CTA: (f = blockIdx.x>>2, s = blockIdx.x&3). Covers points [s*512, s*512+512).
// Thread t: wl = t&63 (8-point group within split), sub = t>>6 (pair subset).
__global__ void __launch_bounds__(THREADS) srp_gather_kernel(
    const float* __restrict__ x, float* __restrict__ out)
{
    __shared__ float sm[2304];   // phase 1: xsm[p*16+slot]; phase 2: psum[4][576]

    const int f   = blockIdx.x >> 2;
    const int s   = blockIdx.x & 3;
    const int tid = threadIdx.x;

    // ---- Stage the 144x16 used x-values: xsm[p*16 + slot] ----
    const float* xf = x + (size_t)f * (NPAIR * KLEN);
    for (int i = tid; i < NPAIR * 16; i += THREADS) {
        int p  = i >> 4;
        int sl = i & 15;
        int k  = (sl < 8) ? sl : (sl + 496);   // slot -> lag
        sm[i] = __ldg(&xf[p * KLEN + k]);
    }
    __syncthreads();

    const int wl  = tid & 63;
    const int sub = tid >> 6;
    const int g8  = s * 64 + wl;
    const int p0  = sub * PSUB;

    const uint4* tv = (const uint4*)(g_tauB + (g8 * NPAIR + p0) * 2); // 18 uint4
    const char*  smb = (const char*)sm + p0 * 64;

    float acc[8];
#pragma unroll
    for (int j = 0; j < 8; j++) acc[j] = 0.0f;

#pragma unroll 3
    for (int u = 0; u < PSUB / 2; u++) {       // 18 iters, 2 pairs each
        uint4 w = __ldg(&tv[u]);
        const char* b0 = smb + u * 128;        // pair 2u
        const char* b1 = b0 + 64;              // pair 2u+1
        acc[0] += *(const float*)(b0 + __byte_perm(w.x, 0, 0x4440));
        acc[1] += *(const float*)(b0 + __byte_perm(w.x, 0, 0x4441));
        acc[2] += *(const float*)(b0 + __byte_perm(w.x, 0, 0x4442));
        acc[3] += *(const float*)(b0 + __byte_perm(w.x, 0, 0x4443));
        acc[4] += *(const float*)(b0 + __byte_perm(w.y, 0, 0x4440));
        acc[5] += *(const float*)(b0 + __byte_perm(w.y, 0, 0x4441));
        acc[6] += *(const float*)(b0 + __byte_perm(w.y, 0, 0x4442));
        acc[7] += *(const float*)(b0 + __byte_perm(w.y, 0, 0x4443));
        acc[0] += *(const float*)(b1 + __byte_perm(w.z, 0, 0x4440));
        acc[1] += *(const float*)(b1 + __byte_perm(w.z, 0, 0x4441));
        acc[2] += *(const float*)(b1 + __byte_perm(w.z, 0, 0x4442));
        acc[3] += *(const float*)(b1 + __byte_perm(w.z, 0, 0x4443));
        acc[4] += *(const float*)(b1 + __byte_perm(w.w, 0, 0x4440));
        acc[5] += *(const float*)(b1 + __byte_perm(w.w, 0, 0x4441));
        acc[6] += *(const float*)(b1 + __byte_perm(w.w, 0, 0x4442));
        acc[7] += *(const float*)(b1 + __byte_perm(w.w, 0, 0x4443));
    }

    // ---- Reduce the 4 pair-subsets through smem (reuse sm) ----
    __syncthreads();                  // everyone done reading xsm
#pragma unroll
    for (int j = 0; j < 8; j++)       // stride-9 layout: conflict-free stores
        sm[sub * 576 + wl * 9 + j] = acc[j];
    __syncthreads();

    float* of = out + (size_t)f * GPTS + s * 512;
#pragma unroll
    for (int e = 0; e < 2; e++) {
        int q = tid * 2 + e;          // local point 0..511
        int a = q + (q >> 3);         // undo stride-9 padding
        float v = sm[a] + sm[576 + a] + sm[1152 + a] + sm[1728 + a];
        of[q] = v;                    // unnormalized partial map
    }
}

// ---------------- per-frame normalization (in place) ----------------
__global__ void __launch_bounds__(THREADS) srp_norm_kernel(float* __restrict__ out)
{
    __shared__ float red_s[THREADS / 32];
    __shared__ float red_m[THREADS / 32];

    const int f   = blockIdx.x;
    const int tid = threadIdx.x;
    float* of = out + (size_t)f * GPTS + tid * 8;

    float4 a = *(const float4*)(of);
    float4 b = *(const float4*)(of + 4);

    float s = a.x + a.y + a.z + a.w + b.x + b.y + b.z + b.w;
    float m = fmaxf(fmaxf(fmaxf(a.x, a.y), fmaxf(a.z, a.w)),
                    fmaxf(fmaxf(b.x, b.y), fmaxf(b.z, b.w)));
#pragma unroll
    for (int o = 16; o > 0; o >>= 1) {
        s += __shfl_xor_sync(0xFFFFFFFFu, s, o);
        m = fmaxf(m, __shfl_xor_sync(0xFFFFFFFFu, m, o));
    }
    int wid  = tid >> 5;
    int lane = tid & 31;
    if (lane == 0) { red_s[wid] = s; red_m[wid] = m; }
    __syncthreads();

    float tot = 0.0f, mm = -3.0e38f;
#pragma unroll
    for (int w = 0; w < THREADS / 32; w++) {
        tot += red_s[w];
        mm = fmaxf(mm, red_m[w]);
    }

    const float EPS = 1e-12f;
    float mean = tot * (1.0f / (float)GPTS);
    float inv  = 1.0f / (mm - mean + EPS);

    a.x = (a.x - mean + EPS) * inv;  a.y = (a.y - mean + EPS) * inv;
    a.z = (a.z - mean + EPS) * inv;  a.w = (a.w - mean + EPS) * inv;
    b.x = (b.x - mean + EPS) * inv;  b.y = (b.y - mean + EPS) * inv;
    b.z = (b.z - mean + EPS) * inv;  b.w = (b.w - mean + EPS) * inv;
    *(float4*)(of)     = a;
    *(float4*)(of + 4) = b;
}

extern "C" void kernel_launch(void* const* d_in, const int* in_sizes, int n_in,
                              void* d_out, int out_size)
{
    const float* x;
    const int*   tau0;
    if (in_sizes[0] == NPAIR * GPTS) {
        tau0 = (const int*)d_in[0];
        x    = (const float*)d_in[1];
    } else {
        x    = (const float*)d_in[0];
        tau0 = (const int*)d_in[1];
    }

    int nframes = out_size / GPTS;

    int pack_words  = 256 * NPAIR * 2;
    int pack_blocks = (pack_words + 255) / 256;
    pre_pack_kernel<<<pack_blocks, 256>>>(tau0);

    srp_gather_kernel<<<nframes * NSPLIT, THREADS>>>(x, (float*)d_out);
    srp_norm_kernel<<<nframes, THREADS>>>((float*)d_out);
}

// round 3
// speedup vs baseline: 1.6333x; 1.6333x over previous
#include <cuda_runtime.h>
#include <stdint.h>

// SRP map on GB300 — round 3.
//
// maps[f,g] = sum_{p<144} x[f, p, tau0[p,g]] (wrapped lags in
// {0..7} U {504..511} -> 16 slots), then per-frame zero-mean + /max.
//
// R3 = R1's coalesced tau reads + R2's 4-instr inner body + 8x grid split:
//  * CTA = (frame, eighth). 2048 CTAs, 1 grid point per thread, single
//    accumulator set -> no cross-subset reduction phase.
//  * tau packed as BYTES slot*4, layout word[c*2048 + g] (c = 4-pair chunk,
//    g fastest): warp lanes read consecutive g -> every tau LDG.32 is one
//    128B transaction. (R2 regressed because its transposed layout made each
//    warp tau load touch 32 lines.)
//  * xsm[p*16+slot]: warp-LDS has p uniform, slot distinct -> distinct
//    banks -> conflict-free.
//  * Inner body per point-pair: PRMT + IADD + LDS[imm] + FFADD.

#define NPAIR   144
#define KLEN    512
#define GPTS    2048
#define THREADS 256
#define NCHUNK  36           // 4-pair chunks

// g_tauB[c*2048 + g]: 4 bytes = slot*4 for pairs 4c..4c+3 at grid point g.
__device__ uint32_t g_tauB[NCHUNK * GPTS];

__global__ void __launch_bounds__(256) pre_pack_kernel(const int* __restrict__ tau0) {
    int i = blockIdx.x * blockDim.x + threadIdx.x;   // = c*2048 + g
    if (i >= NCHUNK * GPTS) return;
    int c = i >> 11;
    int g = i & (GPTS - 1);
    uint32_t v = 0;
#pragma unroll
    for (int j = 0; j < 4; j++) {
        uint32_t t = (uint32_t)tau0[(4 * c + j) * GPTS + g];   // coalesced per j
        v |= ((t & 15u) << 2) << (8 * j);                      // slot*4
    }
    g_tauB[i] = v;
}

// ---------------- main gather kernel ----------------
// CTA: f = blockIdx.x>>3, s = blockIdx.x&7. Thread tid owns point g = s*256+tid.
__global__ void __launch_bounds__(THREADS) srp_gather_kernel(
    const float* __restrict__ x, float* __restrict__ out)
{
    __shared__ float xsm[NPAIR * 16];    // [p*16 + slot], 9216 B

    const int f   = blockIdx.x >> 3;
    const int s   = blockIdx.x & 7;
    const int tid = threadIdx.x;

    // ---- Stage the 144x16 used x-values for this frame ----
    const float* xf = x + (size_t)f * (NPAIR * KLEN);
#pragma unroll
    for (int i = tid; i < NPAIR * 16; i += THREADS) {
        int p  = i >> 4;
        int sl = i & 15;
        int k  = (sl < 8) ? sl : (sl + 496);   // slot -> lag
        xsm[i] = __ldg(&xf[p * KLEN + k]);
    }
    __syncthreads();

    const int g = s * THREADS + tid;
    const uint32_t* tw = g_tauB + g;           // word c at tw[c*2048]
    const char* xb = (const char*)xsm;

    float a0 = 0.0f, a1 = 0.0f, a2 = 0.0f, a3 = 0.0f;

#pragma unroll
    for (int c = 0; c < NCHUNK; c++) {
        uint32_t w = __ldg(&tw[c * GPTS]);
        // pair p = 4c+j lives at byte offset c*256 + j*64 (compile-time imm);
        // byte j of w is slot*4.
        a0 += *(const float*)(xb + (c * 256 +   0) + __byte_perm(w, 0, 0x4440));
        a1 += *(const float*)(xb + (c * 256 +  64) + __byte_perm(w, 0, 0x4441));
        a2 += *(const float*)(xb + (c * 256 + 128) + __byte_perm(w, 0, 0x4442));
        a3 += *(const float*)(xb + (c * 256 + 192) + __byte_perm(w, 0, 0x4443));
    }

    out[(size_t)f * GPTS + g] = (a0 + a1) + (a2 + a3);   // unnormalized
}

// ---------------- per-frame normalization (in place) ----------------
__global__ void __launch_bounds__(THREADS) srp_norm_kernel(float* __restrict__ out)
{
    __shared__ float red_s[THREADS / 32];
    __shared__ float red_m[THREADS / 32];

    const int f   = blockIdx.x;
    const int tid = threadIdx.x;
    float* of = out + (size_t)f * GPTS + tid * 8;

    float4 a = *(const float4*)(of);
    float4 b = *(const float4*)(of + 4);

    float s = a.x + a.y + a.z + a.w + b.x + b.y + b.z + b.w;
    float m = fmaxf(fmaxf(fmaxf(a.x, a.y), fmaxf(a.z, a.w)),
                    fmaxf(fmaxf(b.x, b.y), fmaxf(b.z, b.w)));
#pragma unroll
    for (int o = 16; o > 0; o >>= 1) {
        s += __shfl_xor_sync(0xFFFFFFFFu, s, o);
        m = fmaxf(m, __shfl_xor_sync(0xFFFFFFFFu, m, o));
    }
    int wid  = tid >> 5;
    int lane = tid & 31;
    if (lane == 0) { red_s[wid] = s; red_m[wid] = m; }
    __syncthreads();

    float tot = 0.0f, mm = -3.0e38f;
#pragma unroll
    for (int w = 0; w < THREADS / 32; w++) {
        tot += red_s[w];
        mm = fmaxf(mm, red_m[w]);
    }

    const float EPS = 1e-12f;
    float mean = tot * (1.0f / (float)GPTS);
    float inv  = 1.0f / (mm - mean + EPS);

    a.x = (a.x - mean + EPS) * inv;  a.y = (a.y - mean + EPS) * inv;
    a.z = (a.z - mean + EPS) * inv;  a.w = (a.w - mean + EPS) * inv;
    b.x = (b.x - mean + EPS) * inv;  b.y = (b.y - mean + EPS) * inv;
    b.z = (b.z - mean + EPS) * inv;  b.w = (b.w - mean + EPS) * inv;
    *(float4*)(of)     = a;
    *(float4*)(of + 4) = b;
}

extern "C" void kernel_launch(void* const* d_in, const int* in_sizes, int n_in,
                              void* d_out, int out_size)
{
    const float* x;
    const int*   tau0;
    if (in_sizes[0] == NPAIR * GPTS) {
        tau0 = (const int*)d_in[0];
        x    = (const float*)d_in[1];
    } else {
        x    = (const float*)d_in[0];
        tau0 = (const int*)d_in[1];
    }

    int nframes = out_size / GPTS;

    pre_pack_kernel<<<(NCHUNK * GPTS + 255) / 256, 256>>>(tau0);
    srp_gather_kernel<<<nframes * 8, THREADS>>>(x, (float*)d_out);
    srp_norm_kernel<<<nframes, THREADS>>>((float*)d_out);
}